// round 9
// baseline (speedup 1.0000x reference)
#include <cuda_runtime.h>
#include <math.h>

// Fixed problem shapes
#define NB    8      // batch
#define HW    256    // H = W
#define E     64     // embed channels
#define HID   128    // in/out MLP hidden
#define NH    4      // heads
#define DH    16     // head dim
#define NWIN  128    // B * nwy * nwx = 8*4*4
#define NS    16     // tokens per window (WS*WS)
#define NPIX  256    // pixels per subdomain (16x16)
#define TOKF  (E*NPIX)        // floats per token = 16384
#define NTOK  (NWIN*NS)       // 2048

// Scratch (static device allocations are permitted)
__device__ float g_d [NTOK*TOKF];   // main activation, window layout
__device__ float g_q [NTOK*TOKF];   // q, later reused as attention output o
__device__ float g_k [NTOK*TOKF];
__device__ float g_v [NTOK*TOKF];
__device__ float g_sc[NWIN*NH*NS*NS];

__device__ __forceinline__ float gelu_exact(float a) {
    return 0.5f * a * (1.0f + erff(a * 0.70710678118654752440f));
}

// Map (shifted-space token index) -> original token index.
__device__ __forceinline__ int map_token(int blk, int shift) {
    int bwp = blk >> 4, sp = blk & 15;
    int b = bwp >> 4, wy = (bwp >> 2) & 3, wx = bwp & 3;
    int sy = sp >> 2, sx = sp & 3;
    int gy = ((wy << 2) + sy + shift) & 15;
    int gx = ((wx << 2) + sx + shift) & 15;
    int bw = (b << 4) | ((gy >> 2) << 2) | (gx >> 2);
    int s2 = ((gy & 3) << 2) | (gx & 3);
    return (bw << 4) | s2;
}

// Load token into smem, instance-normalize in place (per channel over 256 pixels).
// (used by k_mlp)
__device__ __forceinline__ void load_and_norm(int tok, float* xs, float* mus, float* rss, int t) {
    const float4* gt = (const float4*)&g_d[(size_t)tok * TOKF];
    float4* xs4 = (float4*)xs;
#pragma unroll
    for (int i = 0; i < 16; i++) xs4[t + 256 * i] = gt[t + 256 * i];
    __syncthreads();
    {
        int ch = t >> 2, seg = t & 3;
        const float* row = &xs[ch * 256 + seg * 64];
        float s = 0.f, q = 0.f;
#pragma unroll
        for (int i = 0; i < 64; i++) { float v = row[i]; s += v; q = fmaf(v, v, q); }
        s += __shfl_xor_sync(0xffffffffu, s, 1); q += __shfl_xor_sync(0xffffffffu, q, 1);
        s += __shfl_xor_sync(0xffffffffu, s, 2); q += __shfl_xor_sync(0xffffffffu, q, 2);
        if (seg == 0) {
            float mu = s * (1.f / 256.f);
            float var = q * (1.f / 256.f) - mu * mu;
            mus[ch] = mu; rss[ch] = rsqrtf(var + 1e-5f);
        }
    }
    __syncthreads();
#pragma unroll
    for (int i = 0; i < 16; i++) {
        int f = t + 256 * i; int ch = f >> 6;
        float4 v = xs4[f]; float mu = mus[ch], r = rss[ch];
        v.x = (v.x - mu) * r; v.y = (v.y - mu) * r;
        v.z = (v.z - mu) * r; v.w = (v.w - mu) * r;
        xs4[f] = v;
    }
    __syncthreads();
}

// ---------------------------------------------------------------------------
// Kernel 1: grid coords + input MLP (5 -> 128 gelu -> 64), window-decompose.
// ---------------------------------------------------------------------------
__global__ __launch_bounds__(256) void k_input(
    const float* __restrict__ v,
    const float* __restrict__ W1, const float* __restrict__ b1,
    const float* __restrict__ W2, const float* __restrict__ b2)
{
    __shared__ float sW1[HID * 5], sb1[HID], sW2t[HID * E], sb2[E];
    int t = threadIdx.x;
    for (int i = t; i < HID * 5; i += 256) sW1[i] = W1[i];
    for (int i = t; i < E * HID; i += 256) {
        int c = i / HID, hd = i % HID;          // W2 is [E][HID] row-major
        sW2t[hd * E + c] = W2[i];               // store as [HID][E]
    }
    if (t < HID) sb1[t] = b1[t];
    if (t < E)   sb2[t] = b2[t];
    __syncthreads();

    int bw = blockIdx.x >> 4, s = blockIdx.x & 15;
    int b = bw >> 4, wy = (bw >> 2) & 3, wx = bw & 3;
    int sy = s >> 2, sx = s & 3;
    int gy = wy * 4 + sy, gx = wx * 4 + sx;
    int y = gy * 16 + (t >> 4), x = gx * 16 + (t & 15);

    float in0 = (float)y + 0.5f;
    float in1 = (float)x + 0.5f;
    int vb = (b * 3 * 256 + y) * 256 + x;
    float in2 = v[vb];
    float in3 = v[vb + 65536];
    float in4 = v[vb + 131072];

    float out[E];
#pragma unroll
    for (int c = 0; c < E; c++) out[c] = sb2[c];

    for (int hd = 0; hd < HID; hd++) {
        const float* w = &sW1[hd * 5];
        float a = sb1[hd];
        a = fmaf(w[0], in0, a); a = fmaf(w[1], in1, a);
        a = fmaf(w[2], in2, a); a = fmaf(w[3], in3, a); a = fmaf(w[4], in4, a);
        float g = gelu_exact(a);
        const float4* wr = (const float4*)&sW2t[hd * E];
#pragma unroll
        for (int c4 = 0; c4 < 16; c4++) {
            float4 w2 = wr[c4];
            out[4 * c4 + 0] = fmaf(w2.x, g, out[4 * c4 + 0]);
            out[4 * c4 + 1] = fmaf(w2.y, g, out[4 * c4 + 1]);
            out[4 * c4 + 2] = fmaf(w2.z, g, out[4 * c4 + 2]);
            out[4 * c4 + 3] = fmaf(w2.w, g, out[4 * c4 + 3]);
        }
    }
    float* dp = &g_d[(size_t)blockIdx.x * TOKF + t];
#pragma unroll
    for (int c = 0; c < E; c++) dp[c * 256] = out[c];
}

// ---------------------------------------------------------------------------
// Kernel 2: instance-norm + Q/K/V projections, register-resident token.
// dyn smem: wq[4096] wk[4096] wv[4096] b[192] mu[64] rs[64] redS[512] redQ[512]
// ---------------------------------------------------------------------------
__global__ __launch_bounds__(256, 2) void k_norm_qkv(
    const float* __restrict__ Wq, const float* __restrict__ bq,
    const float* __restrict__ Wk, const float* __restrict__ bk,
    const float* __restrict__ Wv, const float* __restrict__ bv,
    int shift)
{
    extern __shared__ float sm[];
    float* wqs  = sm;
    float* wks  = wqs + 4096;
    float* wvs  = wks + 4096;
    float* bqs  = wvs + 4096;
    float* bks  = bqs + 64;
    float* bvs  = bks + 64;
    float* mus  = bvs + 64;
    float* rss  = mus + 64;
    float* redS = rss + 64;    // [64 ch][8 warps]
    float* redQ = redS + 512;

    int t = threadIdx.x;
    for (int i = t; i < 4096; i += 256) { wqs[i] = Wq[i]; wks[i] = Wk[i]; wvs[i] = Wv[i]; }
    if (t < 64) { bqs[t] = bq[t]; bks[t] = bk[t]; bvs[t] = bv[t]; }

    int tok = map_token(blockIdx.x, shift);
    const float* gx = &g_d[(size_t)tok * TOKF + t];
    float x[64];
#pragma unroll
    for (int c = 0; c < 64; c++) x[c] = gx[c * 256];

    int lane = t & 31, w = t >> 5;
#pragma unroll
    for (int c = 0; c < 64; c++) {
        float s = x[c], q = x[c] * x[c];
#pragma unroll
        for (int off = 16; off >= 1; off >>= 1) {
            s += __shfl_xor_sync(0xffffffffu, s, off);
            q += __shfl_xor_sync(0xffffffffu, q, off);
        }
        if (lane == 0) { redS[c * 8 + w] = s; redQ[c * 8 + w] = q; }
    }
    __syncthreads();
    if (t < 64) {
        float s = 0.f, q = 0.f;
#pragma unroll
        for (int w8 = 0; w8 < 8; w8++) { s += redS[t * 8 + w8]; q += redQ[t * 8 + w8]; }
        float mu = s * (1.f / 256.f);
        float var = q * (1.f / 256.f) - mu * mu;
        mus[t] = mu; rss[t] = rsqrtf(var + 1e-5f);
    }
    __syncthreads();
#pragma unroll
    for (int c = 0; c < 64; c++) x[c] = (x[c] - mus[c]) * rss[c];

    size_t obase = (size_t)blockIdx.x * TOKF + t;   // outputs in shifted space
    for (int dg = 0; dg < 16; dg++) {
        float aq[4], ak[4], av[4];
#pragma unroll
        for (int u = 0; u < 4; u++) {
            aq[u] = bqs[dg * 4 + u]; ak[u] = bks[dg * 4 + u]; av[u] = bvs[dg * 4 + u];
        }
#pragma unroll
        for (int c4 = 0; c4 < 16; c4++) {
#pragma unroll
            for (int u = 0; u < 4; u++) {
                int row = (dg * 4 + u) * 64 + c4 * 4;
                float4 wq4 = *(const float4*)&wqs[row];
                float4 wk4 = *(const float4*)&wks[row];
                float4 wv4 = *(const float4*)&wvs[row];
                aq[u] = fmaf(wq4.x, x[c4 * 4 + 0], aq[u]);
                aq[u] = fmaf(wq4.y, x[c4 * 4 + 1], aq[u]);
                aq[u] = fmaf(wq4.z, x[c4 * 4 + 2], aq[u]);
                aq[u] = fmaf(wq4.w, x[c4 * 4 + 3], aq[u]);
                ak[u] = fmaf(wk4.x, x[c4 * 4 + 0], ak[u]);
                ak[u] = fmaf(wk4.y, x[c4 * 4 + 1], ak[u]);
                ak[u] = fmaf(wk4.z, x[c4 * 4 + 2], ak[u]);
                ak[u] = fmaf(wk4.w, x[c4 * 4 + 3], ak[u]);
                av[u] = fmaf(wv4.x, x[c4 * 4 + 0], av[u]);
                av[u] = fmaf(wv4.y, x[c4 * 4 + 1], av[u]);
                av[u] = fmaf(wv4.z, x[c4 * 4 + 2], av[u]);
                av[u] = fmaf(wv4.w, x[c4 * 4 + 3], av[u]);
            }
        }
#pragma unroll
        for (int u = 0; u < 4; u++) {
            int d = dg * 4 + u;
            g_q[obase + d * 256] = aq[u];
            g_k[obase + d * 256] = ak[u];
            g_v[obase + d * 256] = av[u];
        }
    }
}

// ---------------------------------------------------------------------------
// Kernel 3: attention scores. Block = (i-group of 4, head, window).
// ---------------------------------------------------------------------------
__global__ __launch_bounds__(256) void k_scores()
{
    int ig = blockIdx.x;            // i-group: query tokens ig*4 .. ig*4+3
    int h  = blockIdx.y;
    int bw = blockIdx.z;
    int t  = threadIdx.x;

    float part[4][16];
#pragma unroll
    for (int u = 0; u < 4; u++)
#pragma unroll
        for (int j = 0; j < 16; j++) part[u][j] = 0.f;

    const size_t hbase = (size_t)(bw * 16) * 64 + h * 16;   // token 0 of window, head ch 0
    for (int c = 0; c < 16; c++) {
        float kr[16];
#pragma unroll
        for (int j = 0; j < 16; j++)
            kr[j] = g_k[(hbase + (size_t)j * 64 + c) * 256 + t];
        float qr[4];
#pragma unroll
        for (int u = 0; u < 4; u++)
            qr[u] = g_q[(hbase + (size_t)(ig * 4 + u) * 64 + c) * 256 + t];
#pragma unroll
        for (int u = 0; u < 4; u++)
#pragma unroll
            for (int j = 0; j < 16; j++)
                part[u][j] = fmaf(qr[u], kr[j], part[u][j]);
    }

    // Reduce each of the 64 partials over 256 pixels: warp tree + smem
    __shared__ float red[8][64];
    int lane = t & 31, w = t >> 5;
#pragma unroll
    for (int u = 0; u < 4; u++) {
#pragma unroll
        for (int j = 0; j < 16; j++) {
            float p = part[u][j];
#pragma unroll
            for (int off = 16; off >= 1; off >>= 1)
                p += __shfl_xor_sync(0xffffffffu, p, off);
            if (lane == 0) red[w][u * 16 + j] = p;
        }
    }
    __syncthreads();
    if (t < 64) {
        int u = t >> 4, j = t & 15;
        float s = 0.f;
#pragma unroll
        for (int w8 = 0; w8 < 8; w8++) s += red[w8][t];
        g_sc[((bw * NH + h) * 16 + ig * 4 + u) * 16 + j] = s * (1.0f / 1024.0f);
    }
}

// ---------------------------------------------------------------------------
// Kernel 4 (v2): softmax + o = A @ v. Block = (window, channel-group of 4).
// 2048 blocks (was 128) -> latency hiding. Channel group lies in one head.
// ---------------------------------------------------------------------------
__global__ __launch_bounds__(256) void k_attnA()
{
    __shared__ float As[16 * 16];
    int bw = blockIdx.x, cg = blockIdx.y;
    int h = cg >> 2;                 // 4 channel-groups per head
    int t = threadIdx.x;

    if (t < 16) {                    // thread t = query token i for this head
        const float* sr = &g_sc[((bw * NH + h) * 16 + t) * 16];
        float m = -1e30f;
#pragma unroll
        for (int j = 0; j < 16; j++) m = fmaxf(m, sr[j]);
        float e[16]; float s = 0.f;
#pragma unroll
        for (int j = 0; j < 16; j++) { e[j] = expf(sr[j] - m); s += e[j]; }
        float inv = 1.f / s;
#pragma unroll
        for (int j = 0; j < 16; j++) As[t * 16 + j] = e[j] * inv;
    }
    __syncthreads();

#pragma unroll
    for (int cc = 0; cc < 4; cc++) {
        int c = cg * 4 + cc;
        float o[16];
#pragma unroll
        for (int i = 0; i < 16; i++) o[i] = 0.f;
#pragma unroll
        for (int j = 0; j < 16; j++) {
            float vv = g_v[(size_t)((bw * 16 + j) * 64 + c) * 256 + t];
#pragma unroll
            for (int i = 0; i < 16; i++)
                o[i] = fmaf(As[i * 16 + j], vv, o[i]);
        }
#pragma unroll
        for (int i = 0; i < 16; i++)
            g_q[(size_t)((bw * 16 + i) * 64 + c) * 256 + t] = o[i];
    }
}

// ---------------------------------------------------------------------------
// Kernel 5: Wo projection + residual add, scattering shifted -> original token.
// ---------------------------------------------------------------------------
__global__ __launch_bounds__(256) void k_attnB(
    const float* __restrict__ Wo, const float* __restrict__ bo, int shift)
{
    __shared__ float wos[E * E], bos[E];
    int t = threadIdx.x;
    for (int i = t; i < E * E; i += 256) wos[i] = Wo[i];
    if (t < E) bos[t] = bo[t];
    __syncthreads();

    int tok = map_token(blockIdx.x, shift);
    float o[E];
    const float* op = &g_q[(size_t)blockIdx.x * TOKF + t];
#pragma unroll
    for (int c = 0; c < E; c++) o[c] = op[c * 256];

    float* dp = &g_d[(size_t)tok * TOKF + t];
    for (int dch = 0; dch < E; dch++) {
        float a = bos[dch];
        const float4* wr = (const float4*)&wos[dch * 64];
#pragma unroll
        for (int c4 = 0; c4 < 16; c4++) {
            float4 w = wr[c4];
            a = fmaf(w.x, o[4 * c4 + 0], a);
            a = fmaf(w.y, o[4 * c4 + 1], a);
            a = fmaf(w.z, o[4 * c4 + 2], a);
            a = fmaf(w.w, o[4 * c4 + 3], a);
        }
        dp[dch * 256] += a;
    }
}

// ---------------------------------------------------------------------------
// Kernel 6: instance-norm + MLP (64->64 gelu ->64) + residual. Block = token.
// ---------------------------------------------------------------------------
__global__ __launch_bounds__(256) void k_mlp(
    const float* __restrict__ W1, const float* __restrict__ b1,
    const float* __restrict__ W2, const float* __restrict__ b2)
{
    extern __shared__ float sm[];
    float* xs  = sm;
    float* w1s = sm + 16384;
    float* w2s = w1s + 4096;
    float* b1s = w2s + 4096;
    float* b2s = b1s + 64;
    float* mus = b2s + 64;
    float* rss = mus + 64;

    int t = threadIdx.x;
    for (int i = t; i < 4096; i += 256) { w1s[i] = W1[i]; w2s[i] = W2[i]; }
    if (t < 64) { b1s[t] = b1[t]; b2s[t] = b2[t]; }

    load_and_norm(blockIdx.x, xs, mus, rss, t);

    float h[E];
    for (int hg = 0; hg < 16; hg++) {
        float a[4];
#pragma unroll
        for (int u = 0; u < 4; u++) a[u] = b1s[hg * 4 + u];
#pragma unroll
        for (int c4 = 0; c4 < 16; c4++) {
            float x0 = xs[(c4 * 4 + 0) * 256 + t];
            float x1 = xs[(c4 * 4 + 1) * 256 + t];
            float x2 = xs[(c4 * 4 + 2) * 256 + t];
            float x3 = xs[(c4 * 4 + 3) * 256 + t];
#pragma unroll
            for (int u = 0; u < 4; u++) {
                float4 w = *(const float4*)&w1s[(hg * 4 + u) * 64 + c4 * 4];
                a[u] = fmaf(w.x, x0, a[u]); a[u] = fmaf(w.y, x1, a[u]);
                a[u] = fmaf(w.z, x2, a[u]); a[u] = fmaf(w.w, x3, a[u]);
            }
        }
#pragma unroll
        for (int u = 0; u < 4; u++) h[hg * 4 + u] = gelu_exact(a[u]);
    }
    float* dp = &g_d[(size_t)blockIdx.x * TOKF + t];
    for (int dch = 0; dch < E; dch++) {
        float a = b2s[dch];
        const float4* wr = (const float4*)&w2s[dch * 64];
#pragma unroll
        for (int c4 = 0; c4 < 16; c4++) {
            float4 w = wr[c4];
            a = fmaf(w.x, h[4 * c4 + 0], a);
            a = fmaf(w.y, h[4 * c4 + 1], a);
            a = fmaf(w.z, h[4 * c4 + 2], a);
            a = fmaf(w.w, h[4 * c4 + 3], a);
        }
        dp[dch * 256] += a;
    }
}

// ---------------------------------------------------------------------------
// Kernel 7: recompose + output MLP (64 -> 128 gelu -> 1).
// ---------------------------------------------------------------------------
__global__ __launch_bounds__(256) void k_output(
    const float* __restrict__ W1, const float* __restrict__ b1,
    const float* __restrict__ W2, const float* __restrict__ b2,
    float* __restrict__ out)
{
    __shared__ float w1s[HID * E], b1s[HID], w2s[HID], b2s[1];
    int t = threadIdx.x;
    for (int i = t; i < HID * E; i += 256) w1s[i] = W1[i];
    if (t < HID) { b1s[t] = b1[t]; w2s[t] = W2[t]; }
    if (t == 0) b2s[0] = b2[0];
    __syncthreads();

    float u[E];
    const float* dp = &g_d[(size_t)blockIdx.x * TOKF + t];
#pragma unroll
    for (int c = 0; c < E; c++) u[c] = dp[c * 256];

    float acc = b2s[0];
    for (int hd = 0; hd < HID; hd++) {
        float a = b1s[hd];
        const float4* wr = (const float4*)&w1s[hd * 64];
#pragma unroll
        for (int c4 = 0; c4 < 16; c4++) {
            float4 w = wr[c4];
            a = fmaf(w.x, u[4 * c4 + 0], a);
            a = fmaf(w.y, u[4 * c4 + 1], a);
            a = fmaf(w.z, u[4 * c4 + 2], a);
            a = fmaf(w.w, u[4 * c4 + 3], a);
        }
        acc = fmaf(w2s[hd], gelu_exact(a), acc);
    }

    int bw = blockIdx.x >> 4, s = blockIdx.x & 15;
    int b = bw >> 4, wy = (bw >> 2) & 3, wx = bw & 3;
    int sy = s >> 2, sx = s & 3;
    int y = (wy * 4 + sy) * 16 + (t >> 4);
    int x = (wx * 4 + sx) * 16 + (t & 15);
    out[(size_t)b * 65536 + y * 256 + x] = acc;
}

// ---------------------------------------------------------------------------
extern "C" void kernel_launch(void* const* d_in, const int* in_sizes, int n_in,
                              void* d_out, int out_size)
{
    const float* v     = (const float*)d_in[0];
    const float* iW1   = (const float*)d_in[1];
    const float* ib1   = (const float*)d_in[2];
    const float* iW2   = (const float*)d_in[3];
    const float* ib2   = (const float*)d_in[4];
    const float* Wq    = (const float*)d_in[5];
    const float* bq    = (const float*)d_in[6];
    const float* Wk    = (const float*)d_in[7];
    const float* bk    = (const float*)d_in[8];
    const float* Wv    = (const float*)d_in[9];
    const float* bv    = (const float*)d_in[10];
    const float* Wo    = (const float*)d_in[11];
    const float* bo    = (const float*)d_in[12];
    const float* mW1   = (const float*)d_in[13];
    const float* mb1   = (const float*)d_in[14];
    const float* mW2   = (const float*)d_in[15];
    const float* mb2   = (const float*)d_in[16];
    const float* oW1   = (const float*)d_in[17];
    const float* ob1   = (const float*)d_in[18];
    const float* oW2   = (const float*)d_in[19];
    const float* ob2   = (const float*)d_in[20];
    float* out = (float*)d_out;

    const size_t sm_qkv = 13632 * sizeof(float);   // 54528 B
    const size_t sm_mlp = 24832 * sizeof(float);   // 99328 B
    cudaFuncSetAttribute(k_norm_qkv, cudaFuncAttributeMaxDynamicSharedMemorySize, (int)sm_qkv);
    cudaFuncSetAttribute(k_mlp,      cudaFuncAttributeMaxDynamicSharedMemorySize, (int)sm_mlp);

    k_input<<<NTOK, 256>>>(v, iW1, ib1, iW2, ib2);

    for (int l = 0; l < 4; l++) {
        int shift = (l & 1) ? 2 : 0;
        k_norm_qkv<<<NTOK, 256, sm_qkv>>>(Wq + l * 4096, bq + l * 64,
                                          Wk + l * 4096, bk + l * 64,
                                          Wv + l * 4096, bv + l * 64, shift);
        k_scores<<<dim3(4, NH, NWIN), 256>>>();
        k_attnA<<<dim3(NWIN, 16), 256>>>();
        k_attnB<<<NTOK, 256>>>(Wo + l * 4096, bo + l * 64, shift);
        k_mlp<<<NTOK, 256, sm_mlp>>>(mW1 + l * 4096, mb1 + l * 64,
                                     mW2 + l * 4096, mb2 + l * 64);
    }

    k_output<<<NTOK, 256>>>(oW1, ob1, oW2, ob2, out);
}

// round 16
// speedup vs baseline: 1.2449x; 1.2449x over previous
#include <cuda_runtime.h>
#include <math.h>

// Fixed problem shapes
#define NB    8      // batch
#define HW    256    // H = W
#define E     64     // embed channels
#define HID   128    // in/out MLP hidden
#define NH    4      // heads
#define DH    16     // head dim
#define NWIN  128    // B * nwy * nwx = 8*4*4
#define NS    16     // tokens per window (WS*WS)
#define NPIX  256    // pixels per subdomain (16x16)
#define TOKF  (E*NPIX)        // floats per token = 16384
#define NTOK  (NWIN*NS)       // 2048

// Scratch (static device allocations are permitted)
__device__ float g_d [NTOK*TOKF];   // main activation, window layout
__device__ float g_q [NTOK*TOKF];   // q, later reused as attention output o
__device__ float g_k [NTOK*TOKF];
__device__ float g_v [NTOK*TOKF];
__device__ float g_sc[NWIN*NH*NS*NS];

__device__ __forceinline__ float gelu_exact(float a) {
    return 0.5f * a * (1.0f + erff(a * 0.70710678118654752440f));
}

// Map (shifted-space token index) -> original token index.
__device__ __forceinline__ int map_token(int blk, int shift) {
    int bwp = blk >> 4, sp = blk & 15;
    int b = bwp >> 4, wy = (bwp >> 2) & 3, wx = bwp & 3;
    int sy = sp >> 2, sx = sp & 3;
    int gy = ((wy << 2) + sy + shift) & 15;
    int gx = ((wx << 2) + sx + shift) & 15;
    int bw = (b << 4) | ((gy >> 2) << 2) | (gx >> 2);
    int s2 = ((gy & 3) << 2) | (gx & 3);
    return (bw << 4) | s2;
}

// Load token into smem, instance-normalize in place (per channel over 256 pixels).
// (used by k_mlp)
__device__ __forceinline__ void load_and_norm(int tok, float* xs, float* mus, float* rss, int t) {
    const float4* gt = (const float4*)&g_d[(size_t)tok * TOKF];
    float4* xs4 = (float4*)xs;
#pragma unroll
    for (int i = 0; i < 16; i++) xs4[t + 256 * i] = gt[t + 256 * i];
    __syncthreads();
    {
        int ch = t >> 2, seg = t & 3;
        const float* row = &xs[ch * 256 + seg * 64];
        float s = 0.f, q = 0.f;
#pragma unroll
        for (int i = 0; i < 64; i++) { float v = row[i]; s += v; q = fmaf(v, v, q); }
        s += __shfl_xor_sync(0xffffffffu, s, 1); q += __shfl_xor_sync(0xffffffffu, q, 1);
        s += __shfl_xor_sync(0xffffffffu, s, 2); q += __shfl_xor_sync(0xffffffffu, q, 2);
        if (seg == 0) {
            float mu = s * (1.f / 256.f);
            float var = q * (1.f / 256.f) - mu * mu;
            mus[ch] = mu; rss[ch] = rsqrtf(var + 1e-5f);
        }
    }
    __syncthreads();
#pragma unroll
    for (int i = 0; i < 16; i++) {
        int f = t + 256 * i; int ch = f >> 6;
        float4 v = xs4[f]; float mu = mus[ch], r = rss[ch];
        v.x = (v.x - mu) * r; v.y = (v.y - mu) * r;
        v.z = (v.z - mu) * r; v.w = (v.w - mu) * r;
        xs4[f] = v;
    }
    __syncthreads();
}

// ---------------------------------------------------------------------------
// Kernel 1: grid coords + input MLP (5 -> 128 gelu -> 64), window-decompose.
// ---------------------------------------------------------------------------
__global__ __launch_bounds__(256) void k_input(
    const float* __restrict__ v,
    const float* __restrict__ W1, const float* __restrict__ b1,
    const float* __restrict__ W2, const float* __restrict__ b2)
{
    __shared__ float sW1[HID * 5], sb1[HID], sW2t[HID * E], sb2[E];
    int t = threadIdx.x;
    for (int i = t; i < HID * 5; i += 256) sW1[i] = W1[i];
    for (int i = t; i < E * HID; i += 256) {
        int c = i / HID, hd = i % HID;          // W2 is [E][HID] row-major
        sW2t[hd * E + c] = W2[i];               // store as [HID][E]
    }
    if (t < HID) sb1[t] = b1[t];
    if (t < E)   sb2[t] = b2[t];
    __syncthreads();

    int bw = blockIdx.x >> 4, s = blockIdx.x & 15;
    int b = bw >> 4, wy = (bw >> 2) & 3, wx = bw & 3;
    int sy = s >> 2, sx = s & 3;
    int gy = wy * 4 + sy, gx = wx * 4 + sx;
    int y = gy * 16 + (t >> 4), x = gx * 16 + (t & 15);

    float in0 = (float)y + 0.5f;
    float in1 = (float)x + 0.5f;
    int vb = (b * 3 * 256 + y) * 256 + x;
    float in2 = v[vb];
    float in3 = v[vb + 65536];
    float in4 = v[vb + 131072];

    float out[E];
#pragma unroll
    for (int c = 0; c < E; c++) out[c] = sb2[c];

    for (int hd = 0; hd < HID; hd++) {
        const float* w = &sW1[hd * 5];
        float a = sb1[hd];
        a = fmaf(w[0], in0, a); a = fmaf(w[1], in1, a);
        a = fmaf(w[2], in2, a); a = fmaf(w[3], in3, a); a = fmaf(w[4], in4, a);
        float g = gelu_exact(a);
        const float4* wr = (const float4*)&sW2t[hd * E];
#pragma unroll
        for (int c4 = 0; c4 < 16; c4++) {
            float4 w2 = wr[c4];
            out[4 * c4 + 0] = fmaf(w2.x, g, out[4 * c4 + 0]);
            out[4 * c4 + 1] = fmaf(w2.y, g, out[4 * c4 + 1]);
            out[4 * c4 + 2] = fmaf(w2.z, g, out[4 * c4 + 2]);
            out[4 * c4 + 3] = fmaf(w2.w, g, out[4 * c4 + 3]);
        }
    }
    float* dp = &g_d[(size_t)blockIdx.x * TOKF + t];
#pragma unroll
    for (int c = 0; c < E; c++) dp[c * 256] = out[c];
}

// ---------------------------------------------------------------------------
// Kernel 2: instance-norm + Q/K/V projections, register-resident token.
// dyn smem: wq[4096] wk[4096] wv[4096] b[192] mu[64] rs[64] redS[512] redQ[512]
// ---------------------------------------------------------------------------
__global__ __launch_bounds__(256, 2) void k_norm_qkv(
    const float* __restrict__ Wq, const float* __restrict__ bq,
    const float* __restrict__ Wk, const float* __restrict__ bk,
    const float* __restrict__ Wv, const float* __restrict__ bv,
    int shift)
{
    extern __shared__ float sm[];
    float* wqs  = sm;
    float* wks  = wqs + 4096;
    float* wvs  = wks + 4096;
    float* bqs  = wvs + 4096;
    float* bks  = bqs + 64;
    float* bvs  = bks + 64;
    float* mus  = bvs + 64;
    float* rss  = mus + 64;
    float* redS = rss + 64;    // [64 ch][8 warps]
    float* redQ = redS + 512;

    int t = threadIdx.x;
    for (int i = t; i < 4096; i += 256) { wqs[i] = Wq[i]; wks[i] = Wk[i]; wvs[i] = Wv[i]; }
    if (t < 64) { bqs[t] = bq[t]; bks[t] = bk[t]; bvs[t] = bv[t]; }

    int tok = map_token(blockIdx.x, shift);
    const float* gx = &g_d[(size_t)tok * TOKF + t];
    float x[64];
#pragma unroll
    for (int c = 0; c < 64; c++) x[c] = gx[c * 256];

    int lane = t & 31, w = t >> 5;
#pragma unroll
    for (int c = 0; c < 64; c++) {
        float s = x[c], q = x[c] * x[c];
#pragma unroll
        for (int off = 16; off >= 1; off >>= 1) {
            s += __shfl_xor_sync(0xffffffffu, s, off);
            q += __shfl_xor_sync(0xffffffffu, q, off);
        }
        if (lane == 0) { redS[c * 8 + w] = s; redQ[c * 8 + w] = q; }
    }
    __syncthreads();
    if (t < 64) {
        float s = 0.f, q = 0.f;
#pragma unroll
        for (int w8 = 0; w8 < 8; w8++) { s += redS[t * 8 + w8]; q += redQ[t * 8 + w8]; }
        float mu = s * (1.f / 256.f);
        float var = q * (1.f / 256.f) - mu * mu;
        mus[t] = mu; rss[t] = rsqrtf(var + 1e-5f);
    }
    __syncthreads();
#pragma unroll
    for (int c = 0; c < 64; c++) x[c] = (x[c] - mus[c]) * rss[c];

    size_t obase = (size_t)blockIdx.x * TOKF + t;   // outputs in shifted space
    for (int dg = 0; dg < 16; dg++) {
        float aq[4], ak[4], av[4];
#pragma unroll
        for (int u = 0; u < 4; u++) {
            aq[u] = bqs[dg * 4 + u]; ak[u] = bks[dg * 4 + u]; av[u] = bvs[dg * 4 + u];
        }
#pragma unroll
        for (int c4 = 0; c4 < 16; c4++) {
#pragma unroll
            for (int u = 0; u < 4; u++) {
                int row = (dg * 4 + u) * 64 + c4 * 4;
                float4 wq4 = *(const float4*)&wqs[row];
                float4 wk4 = *(const float4*)&wks[row];
                float4 wv4 = *(const float4*)&wvs[row];
                aq[u] = fmaf(wq4.x, x[c4 * 4 + 0], aq[u]);
                aq[u] = fmaf(wq4.y, x[c4 * 4 + 1], aq[u]);
                aq[u] = fmaf(wq4.z, x[c4 * 4 + 2], aq[u]);
                aq[u] = fmaf(wq4.w, x[c4 * 4 + 3], aq[u]);
                ak[u] = fmaf(wk4.x, x[c4 * 4 + 0], ak[u]);
                ak[u] = fmaf(wk4.y, x[c4 * 4 + 1], ak[u]);
                ak[u] = fmaf(wk4.z, x[c4 * 4 + 2], ak[u]);
                ak[u] = fmaf(wk4.w, x[c4 * 4 + 3], ak[u]);
                av[u] = fmaf(wv4.x, x[c4 * 4 + 0], av[u]);
                av[u] = fmaf(wv4.y, x[c4 * 4 + 1], av[u]);
                av[u] = fmaf(wv4.z, x[c4 * 4 + 2], av[u]);
                av[u] = fmaf(wv4.w, x[c4 * 4 + 3], av[u]);
            }
        }
#pragma unroll
        for (int u = 0; u < 4; u++) {
            int d = dg * 4 + u;
            g_q[obase + d * 256] = aq[u];
            g_k[obase + d * 256] = ak[u];
            g_v[obase + d * 256] = av[u];
        }
    }
}

// ---------------------------------------------------------------------------
// Kernel 3: attention scores. Block = (i-group of 4, head, window).
// ---------------------------------------------------------------------------
__global__ __launch_bounds__(256) void k_scores()
{
    int ig = blockIdx.x;            // i-group: query tokens ig*4 .. ig*4+3
    int h  = blockIdx.y;
    int bw = blockIdx.z;
    int t  = threadIdx.x;

    float part[4][16];
#pragma unroll
    for (int u = 0; u < 4; u++)
#pragma unroll
        for (int j = 0; j < 16; j++) part[u][j] = 0.f;

    const size_t hbase = (size_t)(bw * 16) * 64 + h * 16;   // token 0 of window, head ch 0
    for (int c = 0; c < 16; c++) {
        float kr[16];
#pragma unroll
        for (int j = 0; j < 16; j++)
            kr[j] = g_k[(hbase + (size_t)j * 64 + c) * 256 + t];
        float qr[4];
#pragma unroll
        for (int u = 0; u < 4; u++)
            qr[u] = g_q[(hbase + (size_t)(ig * 4 + u) * 64 + c) * 256 + t];
#pragma unroll
        for (int u = 0; u < 4; u++)
#pragma unroll
            for (int j = 0; j < 16; j++)
                part[u][j] = fmaf(qr[u], kr[j], part[u][j]);
    }

    // Reduce each of the 64 partials over 256 pixels: warp tree + smem
    __shared__ float red[8][64];
    int lane = t & 31, w = t >> 5;
#pragma unroll
    for (int u = 0; u < 4; u++) {
#pragma unroll
        for (int j = 0; j < 16; j++) {
            float p = part[u][j];
#pragma unroll
            for (int off = 16; off >= 1; off >>= 1)
                p += __shfl_xor_sync(0xffffffffu, p, off);
            if (lane == 0) red[w][u * 16 + j] = p;
        }
    }
    __syncthreads();
    if (t < 64) {
        int u = t >> 4, j = t & 15;
        float s = 0.f;
#pragma unroll
        for (int w8 = 0; w8 < 8; w8++) s += red[w8][t];
        g_sc[((bw * NH + h) * 16 + ig * 4 + u) * 16 + j] = s * (1.0f / 1024.0f);
    }
}

// ---------------------------------------------------------------------------
// Kernel 4 (v3): softmax + o = A @ v. Block = one window, 1024 threads.
// t = tid & 255 (pixel), h = tid >> 8 (head, owning its 16 channels).
// Streams the window's v contiguously exactly once (like v1) but with 32
// warps/SM for latency hiding (v1 had only 8). Same accumulation order.
// ---------------------------------------------------------------------------
__global__ __launch_bounds__(1024) void k_attnA()
{
    __shared__ float As[NH][16 * 16];
    int bw = blockIdx.x;
    int tid = threadIdx.x;
    int t = tid & 255;              // pixel
    int h = tid >> 8;               // head = channel quarter

    if (t < 16) {                   // thread (h, i=t) does softmax row i of head h
        const float* sr = &g_sc[((bw * NH + h) * 16 + t) * 16];
        float m = -1e30f;
#pragma unroll
        for (int j = 0; j < 16; j++) m = fmaxf(m, sr[j]);
        float e[16]; float s = 0.f;
#pragma unroll
        for (int j = 0; j < 16; j++) { e[j] = expf(sr[j] - m); s += e[j]; }
        float inv = 1.f / s;
#pragma unroll
        for (int j = 0; j < 16; j++) As[h][t * 16 + j] = e[j] * inv;
    }
    __syncthreads();

    for (int cc = 0; cc < 16; cc++) {
        int c = h * 16 + cc;
        float o[16];
#pragma unroll
        for (int i = 0; i < 16; i++) o[i] = 0.f;
#pragma unroll
        for (int j = 0; j < 16; j++) {
            float vv = g_v[(size_t)((bw * 16 + j) * 64 + c) * 256 + t];
#pragma unroll
            for (int i = 0; i < 16; i++)
                o[i] = fmaf(As[h][i * 16 + j], vv, o[i]);
        }
#pragma unroll
        for (int i = 0; i < 16; i++)
            g_q[(size_t)((bw * 16 + i) * 64 + c) * 256 + t] = o[i];
    }
}

// ---------------------------------------------------------------------------
// Kernel 5: Wo projection + residual add, scattering shifted -> original token.
// ---------------------------------------------------------------------------
__global__ __launch_bounds__(256) void k_attnB(
    const float* __restrict__ Wo, const float* __restrict__ bo, int shift)
{
    __shared__ float wos[E * E], bos[E];
    int t = threadIdx.x;
    for (int i = t; i < E * E; i += 256) wos[i] = Wo[i];
    if (t < E) bos[t] = bo[t];
    __syncthreads();

    int tok = map_token(blockIdx.x, shift);
    float o[E];
    const float* op = &g_q[(size_t)blockIdx.x * TOKF + t];
#pragma unroll
    for (int c = 0; c < E; c++) o[c] = op[c * 256];

    float* dp = &g_d[(size_t)tok * TOKF + t];
    for (int dch = 0; dch < E; dch++) {
        float a = bos[dch];
        const float4* wr = (const float4*)&wos[dch * 64];
#pragma unroll
        for (int c4 = 0; c4 < 16; c4++) {
            float4 w = wr[c4];
            a = fmaf(w.x, o[4 * c4 + 0], a);
            a = fmaf(w.y, o[4 * c4 + 1], a);
            a = fmaf(w.z, o[4 * c4 + 2], a);
            a = fmaf(w.w, o[4 * c4 + 3], a);
        }
        dp[dch * 256] += a;
    }
}

// ---------------------------------------------------------------------------
// Kernel 6: instance-norm + MLP (64->64 gelu ->64) + residual. Block = token.
// ---------------------------------------------------------------------------
__global__ __launch_bounds__(256) void k_mlp(
    const float* __restrict__ W1, const float* __restrict__ b1,
    const float* __restrict__ W2, const float* __restrict__ b2)
{
    extern __shared__ float sm[];
    float* xs  = sm;
    float* w1s = sm + 16384;
    float* w2s = w1s + 4096;
    float* b1s = w2s + 4096;
    float* b2s = b1s + 64;
    float* mus = b2s + 64;
    float* rss = mus + 64;

    int t = threadIdx.x;
    for (int i = t; i < 4096; i += 256) { w1s[i] = W1[i]; w2s[i] = W2[i]; }
    if (t < 64) { b1s[t] = b1[t]; b2s[t] = b2[t]; }

    load_and_norm(blockIdx.x, xs, mus, rss, t);

    float h[E];
    for (int hg = 0; hg < 16; hg++) {
        float a[4];
#pragma unroll
        for (int u = 0; u < 4; u++) a[u] = b1s[hg * 4 + u];
#pragma unroll
        for (int c4 = 0; c4 < 16; c4++) {
            float x0 = xs[(c4 * 4 + 0) * 256 + t];
            float x1 = xs[(c4 * 4 + 1) * 256 + t];
            float x2 = xs[(c4 * 4 + 2) * 256 + t];
            float x3 = xs[(c4 * 4 + 3) * 256 + t];
#pragma unroll
            for (int u = 0; u < 4; u++) {
                float4 w = *(const float4*)&w1s[(hg * 4 + u) * 64 + c4 * 4];
                a[u] = fmaf(w.x, x0, a[u]); a[u] = fmaf(w.y, x1, a[u]);
                a[u] = fmaf(w.z, x2, a[u]); a[u] = fmaf(w.w, x3, a[u]);
            }
        }
#pragma unroll
        for (int u = 0; u < 4; u++) h[hg * 4 + u] = gelu_exact(a[u]);
    }
    float* dp = &g_d[(size_t)blockIdx.x * TOKF + t];
    for (int dch = 0; dch < E; dch++) {
        float a = b2s[dch];
        const float4* wr = (const float4*)&w2s[dch * 64];
#pragma unroll
        for (int c4 = 0; c4 < 16; c4++) {
            float4 w = wr[c4];
            a = fmaf(w.x, h[4 * c4 + 0], a);
            a = fmaf(w.y, h[4 * c4 + 1], a);
            a = fmaf(w.z, h[4 * c4 + 2], a);
            a = fmaf(w.w, h[4 * c4 + 3], a);
        }
        dp[dch * 256] += a;
    }
}

// ---------------------------------------------------------------------------
// Kernel 7: recompose + output MLP (64 -> 128 gelu -> 1).
// ---------------------------------------------------------------------------
__global__ __launch_bounds__(256) void k_output(
    const float* __restrict__ W1, const float* __restrict__ b1,
    const float* __restrict__ W2, const float* __restrict__ b2,
    float* __restrict__ out)
{
    __shared__ float w1s[HID * E], b1s[HID], w2s[HID], b2s[1];
    int t = threadIdx.x;
    for (int i = t; i < HID * E; i += 256) w1s[i] = W1[i];
    if (t < HID) { b1s[t] = b1[t]; w2s[t] = W2[t]; }
    if (t == 0) b2s[0] = b2[0];
    __syncthreads();

    float u[E];
    const float* dp = &g_d[(size_t)blockIdx.x * TOKF + t];
#pragma unroll
    for (int c = 0; c < E; c++) u[c] = dp[c * 256];

    float acc = b2s[0];
    for (int hd = 0; hd < HID; hd++) {
        float a = b1s[hd];
        const float4* wr = (const float4*)&w1s[hd * 64];
#pragma unroll
        for (int c4 = 0; c4 < 16; c4++) {
            float4 w = wr[c4];
            a = fmaf(w.x, u[4 * c4 + 0], a);
            a = fmaf(w.y, u[4 * c4 + 1], a);
            a = fmaf(w.z, u[4 * c4 + 2], a);
            a = fmaf(w.w, u[4 * c4 + 3], a);
        }
        acc = fmaf(w2s[hd], gelu_exact(a), acc);
    }

    int bw = blockIdx.x >> 4, s = blockIdx.x & 15;
    int b = bw >> 4, wy = (bw >> 2) & 3, wx = bw & 3;
    int sy = s >> 2, sx = s & 3;
    int y = (wy * 4 + sy) * 16 + (t >> 4);
    int x = (wx * 4 + sx) * 16 + (t & 15);
    out[(size_t)b * 65536 + y * 256 + x] = acc;
}

// ---------------------------------------------------------------------------
extern "C" void kernel_launch(void* const* d_in, const int* in_sizes, int n_in,
                              void* d_out, int out_size)
{
    const float* v     = (const float*)d_in[0];
    const float* iW1   = (const float*)d_in[1];
    const float* ib1   = (const float*)d_in[2];
    const float* iW2   = (const float*)d_in[3];
    const float* ib2   = (const float*)d_in[4];
    const float* Wq    = (const float*)d_in[5];
    const float* bq    = (const float*)d_in[6];
    const float* Wk    = (const float*)d_in[7];
    const float* bk    = (const float*)d_in[8];
    const float* Wv    = (const float*)d_in[9];
    const float* bv    = (const float*)d_in[10];
    const float* Wo    = (const float*)d_in[11];
    const float* bo    = (const float*)d_in[12];
    const float* mW1   = (const float*)d_in[13];
    const float* mb1   = (const float*)d_in[14];
    const float* mW2   = (const float*)d_in[15];
    const float* mb2   = (const float*)d_in[16];
    const float* oW1   = (const float*)d_in[17];
    const float* ob1   = (const float*)d_in[18];
    const float* oW2   = (const float*)d_in[19];
    const float* ob2   = (const float*)d_in[20];
    float* out = (float*)d_out;

    const size_t sm_qkv = 13632 * sizeof(float);   // 54528 B
    const size_t sm_mlp = 24832 * sizeof(float);   // 99328 B
    cudaFuncSetAttribute(k_norm_qkv, cudaFuncAttributeMaxDynamicSharedMemorySize, (int)sm_qkv);
    cudaFuncSetAttribute(k_mlp,      cudaFuncAttributeMaxDynamicSharedMemorySize, (int)sm_mlp);

    k_input<<<NTOK, 256>>>(v, iW1, ib1, iW2, ib2);

    for (int l = 0; l < 4; l++) {
        int shift = (l & 1) ? 2 : 0;
        k_norm_qkv<<<NTOK, 256, sm_qkv>>>(Wq + l * 4096, bq + l * 64,
                                          Wk + l * 4096, bk + l * 64,
                                          Wv + l * 4096, bv + l * 64, shift);
        k_scores<<<dim3(4, NH, NWIN), 256>>>();
        k_attnA<<<NWIN, 1024>>>();
        k_attnB<<<NTOK, 256>>>(Wo + l * 4096, bo + l * 64, shift);
        k_mlp<<<NTOK, 256, sm_mlp>>>(mW1 + l * 4096, mb1 + l * 64,
                                     mW2 + l * 4096, mb2 + l * 64);
    }

    k_output<<<NTOK, 256>>>(oW1, ob1, oW2, ob2, out);
}

// round 17
// speedup vs baseline: 1.6260x; 1.3061x over previous
#include <cuda_runtime.h>
#include <math.h>

// Fixed problem shapes
#define NB    8      // batch
#define HW    256    // H = W
#define E     64     // embed channels
#define HID   128    // in/out MLP hidden
#define NH    4      // heads
#define DH    16     // head dim
#define NWIN  128    // B * nwy * nwx = 8*4*4
#define NS    16     // tokens per window (WS*WS)
#define NPIX  256    // pixels per subdomain (16x16)
#define TOKF  (E*NPIX)        // floats per token = 16384
#define NTOK  (NWIN*NS)       // 2048

// Scratch (static device allocations are permitted)
__device__ float g_d [NTOK*TOKF];   // main activation, window layout
__device__ float g_q [NTOK*TOKF];   // q, later reused as attention output o
__device__ float g_k [NTOK*TOKF];
__device__ float g_v [NTOK*TOKF];
__device__ float g_sc[NWIN*NH*NS*NS];

__device__ __forceinline__ float gelu_exact(float a) {
    return 0.5f * a * (1.0f + erff(a * 0.70710678118654752440f));
}

// Map (shifted-space token index) -> original token index.
__device__ __forceinline__ int map_token(int blk, int shift) {
    int bwp = blk >> 4, sp = blk & 15;
    int b = bwp >> 4, wy = (bwp >> 2) & 3, wx = bwp & 3;
    int sy = sp >> 2, sx = sp & 3;
    int gy = ((wy << 2) + sy + shift) & 15;
    int gx = ((wx << 2) + sx + shift) & 15;
    int bw = (b << 4) | ((gy >> 2) << 2) | (gx >> 2);
    int s2 = ((gy & 3) << 2) | (gx & 3);
    return (bw << 4) | s2;
}

// Load token into smem, instance-normalize in place (per channel over 256 pixels).
// (used by k_mlp)
__device__ __forceinline__ void load_and_norm(int tok, float* xs, float* mus, float* rss, int t) {
    const float4* gt = (const float4*)&g_d[(size_t)tok * TOKF];
    float4* xs4 = (float4*)xs;
#pragma unroll
    for (int i = 0; i < 16; i++) xs4[t + 256 * i] = gt[t + 256 * i];
    __syncthreads();
    {
        int ch = t >> 2, seg = t & 3;
        const float* row = &xs[ch * 256 + seg * 64];
        float s = 0.f, q = 0.f;
#pragma unroll
        for (int i = 0; i < 64; i++) { float v = row[i]; s += v; q = fmaf(v, v, q); }
        s += __shfl_xor_sync(0xffffffffu, s, 1); q += __shfl_xor_sync(0xffffffffu, q, 1);
        s += __shfl_xor_sync(0xffffffffu, s, 2); q += __shfl_xor_sync(0xffffffffu, q, 2);
        if (seg == 0) {
            float mu = s * (1.f / 256.f);
            float var = q * (1.f / 256.f) - mu * mu;
            mus[ch] = mu; rss[ch] = rsqrtf(var + 1e-5f);
        }
    }
    __syncthreads();
#pragma unroll
    for (int i = 0; i < 16; i++) {
        int f = t + 256 * i; int ch = f >> 6;
        float4 v = xs4[f]; float mu = mus[ch], r = rss[ch];
        v.x = (v.x - mu) * r; v.y = (v.y - mu) * r;
        v.z = (v.z - mu) * r; v.w = (v.w - mu) * r;
        xs4[f] = v;
    }
    __syncthreads();
}

// ---------------------------------------------------------------------------
// Kernel 1: grid coords + input MLP (5 -> 128 gelu -> 64), window-decompose.
// ---------------------------------------------------------------------------
__global__ __launch_bounds__(256) void k_input(
    const float* __restrict__ v,
    const float* __restrict__ W1, const float* __restrict__ b1,
    const float* __restrict__ W2, const float* __restrict__ b2)
{
    __shared__ float sW1[HID * 5], sb1[HID], sW2t[HID * E], sb2[E];
    int t = threadIdx.x;
    for (int i = t; i < HID * 5; i += 256) sW1[i] = W1[i];
    for (int i = t; i < E * HID; i += 256) {
        int c = i / HID, hd = i % HID;          // W2 is [E][HID] row-major
        sW2t[hd * E + c] = W2[i];               // store as [HID][E]
    }
    if (t < HID) sb1[t] = b1[t];
    if (t < E)   sb2[t] = b2[t];
    __syncthreads();

    int bw = blockIdx.x >> 4, s = blockIdx.x & 15;
    int b = bw >> 4, wy = (bw >> 2) & 3, wx = bw & 3;
    int sy = s >> 2, sx = s & 3;
    int gy = wy * 4 + sy, gx = wx * 4 + sx;
    int y = gy * 16 + (t >> 4), x = gx * 16 + (t & 15);

    float in0 = (float)y + 0.5f;
    float in1 = (float)x + 0.5f;
    int vb = (b * 3 * 256 + y) * 256 + x;
    float in2 = v[vb];
    float in3 = v[vb + 65536];
    float in4 = v[vb + 131072];

    float out[E];
#pragma unroll
    for (int c = 0; c < E; c++) out[c] = sb2[c];

    for (int hd = 0; hd < HID; hd++) {
        const float* w = &sW1[hd * 5];
        float a = sb1[hd];
        a = fmaf(w[0], in0, a); a = fmaf(w[1], in1, a);
        a = fmaf(w[2], in2, a); a = fmaf(w[3], in3, a); a = fmaf(w[4], in4, a);
        float g = gelu_exact(a);
        const float4* wr = (const float4*)&sW2t[hd * E];
#pragma unroll
        for (int c4 = 0; c4 < 16; c4++) {
            float4 w2 = wr[c4];
            out[4 * c4 + 0] = fmaf(w2.x, g, out[4 * c4 + 0]);
            out[4 * c4 + 1] = fmaf(w2.y, g, out[4 * c4 + 1]);
            out[4 * c4 + 2] = fmaf(w2.z, g, out[4 * c4 + 2]);
            out[4 * c4 + 3] = fmaf(w2.w, g, out[4 * c4 + 3]);
        }
    }
    float* dp = &g_d[(size_t)blockIdx.x * TOKF + t];
#pragma unroll
    for (int c = 0; c < E; c++) dp[c * 256] = out[c];
}

// ---------------------------------------------------------------------------
// Kernel 2: instance-norm + Q/K/V projections, register-resident token.
// dyn smem: wq[4096] wk[4096] wv[4096] b[192] mu[64] rs[64] redS[512] redQ[512]
// ---------------------------------------------------------------------------
__global__ __launch_bounds__(256, 2) void k_norm_qkv(
    const float* __restrict__ Wq, const float* __restrict__ bq,
    const float* __restrict__ Wk, const float* __restrict__ bk,
    const float* __restrict__ Wv, const float* __restrict__ bv,
    int shift)
{
    extern __shared__ float sm[];
    float* wqs  = sm;
    float* wks  = wqs + 4096;
    float* wvs  = wks + 4096;
    float* bqs  = wvs + 4096;
    float* bks  = bqs + 64;
    float* bvs  = bks + 64;
    float* mus  = bvs + 64;
    float* rss  = mus + 64;
    float* redS = rss + 64;    // [64 ch][8 warps]
    float* redQ = redS + 512;

    int t = threadIdx.x;
    for (int i = t; i < 4096; i += 256) { wqs[i] = Wq[i]; wks[i] = Wk[i]; wvs[i] = Wv[i]; }
    if (t < 64) { bqs[t] = bq[t]; bks[t] = bk[t]; bvs[t] = bv[t]; }

    int tok = map_token(blockIdx.x, shift);
    const float* gx = &g_d[(size_t)tok * TOKF + t];
    float x[64];
#pragma unroll
    for (int c = 0; c < 64; c++) x[c] = gx[c * 256];

    int lane = t & 31, w = t >> 5;
#pragma unroll
    for (int c = 0; c < 64; c++) {
        float s = x[c], q = x[c] * x[c];
#pragma unroll
        for (int off = 16; off >= 1; off >>= 1) {
            s += __shfl_xor_sync(0xffffffffu, s, off);
            q += __shfl_xor_sync(0xffffffffu, q, off);
        }
        if (lane == 0) { redS[c * 8 + w] = s; redQ[c * 8 + w] = q; }
    }
    __syncthreads();
    if (t < 64) {
        float s = 0.f, q = 0.f;
#pragma unroll
        for (int w8 = 0; w8 < 8; w8++) { s += redS[t * 8 + w8]; q += redQ[t * 8 + w8]; }
        float mu = s * (1.f / 256.f);
        float var = q * (1.f / 256.f) - mu * mu;
        mus[t] = mu; rss[t] = rsqrtf(var + 1e-5f);
    }
    __syncthreads();
#pragma unroll
    for (int c = 0; c < 64; c++) x[c] = (x[c] - mus[c]) * rss[c];

    size_t obase = (size_t)blockIdx.x * TOKF + t;   // outputs in shifted space
    for (int dg = 0; dg < 16; dg++) {
        float aq[4], ak[4], av[4];
#pragma unroll
        for (int u = 0; u < 4; u++) {
            aq[u] = bqs[dg * 4 + u]; ak[u] = bks[dg * 4 + u]; av[u] = bvs[dg * 4 + u];
        }
#pragma unroll
        for (int c4 = 0; c4 < 16; c4++) {
#pragma unroll
            for (int u = 0; u < 4; u++) {
                int row = (dg * 4 + u) * 64 + c4 * 4;
                float4 wq4 = *(const float4*)&wqs[row];
                float4 wk4 = *(const float4*)&wks[row];
                float4 wv4 = *(const float4*)&wvs[row];
                aq[u] = fmaf(wq4.x, x[c4 * 4 + 0], aq[u]);
                aq[u] = fmaf(wq4.y, x[c4 * 4 + 1], aq[u]);
                aq[u] = fmaf(wq4.z, x[c4 * 4 + 2], aq[u]);
                aq[u] = fmaf(wq4.w, x[c4 * 4 + 3], aq[u]);
                ak[u] = fmaf(wk4.x, x[c4 * 4 + 0], ak[u]);
                ak[u] = fmaf(wk4.y, x[c4 * 4 + 1], ak[u]);
                ak[u] = fmaf(wk4.z, x[c4 * 4 + 2], ak[u]);
                ak[u] = fmaf(wk4.w, x[c4 * 4 + 3], ak[u]);
                av[u] = fmaf(wv4.x, x[c4 * 4 + 0], av[u]);
                av[u] = fmaf(wv4.y, x[c4 * 4 + 1], av[u]);
                av[u] = fmaf(wv4.z, x[c4 * 4 + 2], av[u]);
                av[u] = fmaf(wv4.w, x[c4 * 4 + 3], av[u]);
            }
        }
#pragma unroll
        for (int u = 0; u < 4; u++) {
            int d = dg * 4 + u;
            g_q[obase + d * 256] = aq[u];
            g_k[obase + d * 256] = ak[u];
            g_v[obase + d * 256] = av[u];
        }
    }
}

// ---------------------------------------------------------------------------
// Kernel 3: attention scores. Block = (i-group of 4, head, window).
// ---------------------------------------------------------------------------
__global__ __launch_bounds__(256) void k_scores()
{
    int ig = blockIdx.x;            // i-group: query tokens ig*4 .. ig*4+3
    int h  = blockIdx.y;
    int bw = blockIdx.z;
    int t  = threadIdx.x;

    float part[4][16];
#pragma unroll
    for (int u = 0; u < 4; u++)
#pragma unroll
        for (int j = 0; j < 16; j++) part[u][j] = 0.f;

    const size_t hbase = (size_t)(bw * 16) * 64 + h * 16;   // token 0 of window, head ch 0
    for (int c = 0; c < 16; c++) {
        float kr[16];
#pragma unroll
        for (int j = 0; j < 16; j++)
            kr[j] = g_k[(hbase + (size_t)j * 64 + c) * 256 + t];
        float qr[4];
#pragma unroll
        for (int u = 0; u < 4; u++)
            qr[u] = g_q[(hbase + (size_t)(ig * 4 + u) * 64 + c) * 256 + t];
#pragma unroll
        for (int u = 0; u < 4; u++)
#pragma unroll
            for (int j = 0; j < 16; j++)
                part[u][j] = fmaf(qr[u], kr[j], part[u][j]);
    }

    // Reduce each of the 64 partials over 256 pixels: warp tree + smem
    __shared__ float red[8][64];
    int lane = t & 31, w = t >> 5;
#pragma unroll
    for (int u = 0; u < 4; u++) {
#pragma unroll
        for (int j = 0; j < 16; j++) {
            float p = part[u][j];
#pragma unroll
            for (int off = 16; off >= 1; off >>= 1)
                p += __shfl_xor_sync(0xffffffffu, p, off);
            if (lane == 0) red[w][u * 16 + j] = p;
        }
    }
    __syncthreads();
    if (t < 64) {
        int u = t >> 4, j = t & 15;
        float s = 0.f;
#pragma unroll
        for (int w8 = 0; w8 < 8; w8++) s += red[w8][t];
        g_sc[((bw * NH + h) * 16 + ig * 4 + u) * 16 + j] = s * (1.0f / 1024.0f);
    }
}

// ---------------------------------------------------------------------------
// Kernel 4 (v4): softmax + o = A @ v. Block = one window, 512 threads.
// t = tid & 255 (pixel), half = tid >> 8; each half handles 32 channels.
// __launch_bounds__(512) -> 128-reg cap: o[16] + temps fit with headroom,
// NO SPILLS (v3's 1024-thread 64-reg cap spilled o[16] -> 11x DRAM traffic).
// Streaming layout identical to v1 (v read once, contiguous), 16 warps/SM.
// ---------------------------------------------------------------------------
__global__ __launch_bounds__(512) void k_attnA()
{
    __shared__ float As[NH][16 * 16];
    int bw = blockIdx.x;
    int tid = threadIdx.x;
    int t = tid & 255;              // pixel
    int half = tid >> 8;            // channel half: 0 -> c 0..31, 1 -> c 32..63

    if (tid < 64) {                 // thread = (head h, query i): softmax row
        int h = tid >> 4, i = tid & 15;
        const float* sr = &g_sc[((bw * NH + h) * 16 + i) * 16];
        float m = -1e30f;
#pragma unroll
        for (int j = 0; j < 16; j++) m = fmaxf(m, sr[j]);
        float e[16]; float s = 0.f;
#pragma unroll
        for (int j = 0; j < 16; j++) { e[j] = expf(sr[j] - m); s += e[j]; }
        float inv = 1.f / s;
#pragma unroll
        for (int j = 0; j < 16; j++) As[h][i * 16 + j] = e[j] * inv;
    }
    __syncthreads();

    for (int cc = 0; cc < 32; cc++) {
        int c = half * 32 + cc;
        const float* ah = As[c >> 4];
        float o[16];
#pragma unroll
        for (int i = 0; i < 16; i++) o[i] = 0.f;
#pragma unroll
        for (int j = 0; j < 16; j++) {
            float vv = g_v[(size_t)((bw * 16 + j) * 64 + c) * 256 + t];
#pragma unroll
            for (int i = 0; i < 16; i++)
                o[i] = fmaf(ah[i * 16 + j], vv, o[i]);
        }
#pragma unroll
        for (int i = 0; i < 16; i++)
            g_q[(size_t)((bw * 16 + i) * 64 + c) * 256 + t] = o[i];
    }
}

// ---------------------------------------------------------------------------
// Kernel 5: Wo projection + residual add, scattering shifted -> original token.
// ---------------------------------------------------------------------------
__global__ __launch_bounds__(256) void k_attnB(
    const float* __restrict__ Wo, const float* __restrict__ bo, int shift)
{
    __shared__ float wos[E * E], bos[E];
    int t = threadIdx.x;
    for (int i = t; i < E * E; i += 256) wos[i] = Wo[i];
    if (t < E) bos[t] = bo[t];
    __syncthreads();

    int tok = map_token(blockIdx.x, shift);
    float o[E];
    const float* op = &g_q[(size_t)blockIdx.x * TOKF + t];
#pragma unroll
    for (int c = 0; c < E; c++) o[c] = op[c * 256];

    float* dp = &g_d[(size_t)tok * TOKF + t];
    for (int dch = 0; dch < E; dch++) {
        float a = bos[dch];
        const float4* wr = (const float4*)&wos[dch * 64];
#pragma unroll
        for (int c4 = 0; c4 < 16; c4++) {
            float4 w = wr[c4];
            a = fmaf(w.x, o[4 * c4 + 0], a);
            a = fmaf(w.y, o[4 * c4 + 1], a);
            a = fmaf(w.z, o[4 * c4 + 2], a);
            a = fmaf(w.w, o[4 * c4 + 3], a);
        }
        dp[dch * 256] += a;
    }
}

// ---------------------------------------------------------------------------
// Kernel 6: instance-norm + MLP (64->64 gelu ->64) + residual. Block = token.
// ---------------------------------------------------------------------------
__global__ __launch_bounds__(256) void k_mlp(
    const float* __restrict__ W1, const float* __restrict__ b1,
    const float* __restrict__ W2, const float* __restrict__ b2)
{
    extern __shared__ float sm[];
    float* xs  = sm;
    float* w1s = sm + 16384;
    float* w2s = w1s + 4096;
    float* b1s = w2s + 4096;
    float* b2s = b1s + 64;
    float* mus = b2s + 64;
    float* rss = mus + 64;

    int t = threadIdx.x;
    for (int i = t; i < 4096; i += 256) { w1s[i] = W1[i]; w2s[i] = W2[i]; }
    if (t < 64) { b1s[t] = b1[t]; b2s[t] = b2[t]; }

    load_and_norm(blockIdx.x, xs, mus, rss, t);

    float h[E];
    for (int hg = 0; hg < 16; hg++) {
        float a[4];
#pragma unroll
        for (int u = 0; u < 4; u++) a[u] = b1s[hg * 4 + u];
#pragma unroll
        for (int c4 = 0; c4 < 16; c4++) {
            float x0 = xs[(c4 * 4 + 0) * 256 + t];
            float x1 = xs[(c4 * 4 + 1) * 256 + t];
            float x2 = xs[(c4 * 4 + 2) * 256 + t];
            float x3 = xs[(c4 * 4 + 3) * 256 + t];
#pragma unroll
            for (int u = 0; u < 4; u++) {
                float4 w = *(const float4*)&w1s[(hg * 4 + u) * 64 + c4 * 4];
                a[u] = fmaf(w.x, x0, a[u]); a[u] = fmaf(w.y, x1, a[u]);
                a[u] = fmaf(w.z, x2, a[u]); a[u] = fmaf(w.w, x3, a[u]);
            }
        }
#pragma unroll
        for (int u = 0; u < 4; u++) h[hg * 4 + u] = gelu_exact(a[u]);
    }
    float* dp = &g_d[(size_t)blockIdx.x * TOKF + t];
    for (int dch = 0; dch < E; dch++) {
        float a = b2s[dch];
        const float4* wr = (const float4*)&w2s[dch * 64];
#pragma unroll
        for (int c4 = 0; c4 < 16; c4++) {
            float4 w = wr[c4];
            a = fmaf(w.x, h[4 * c4 + 0], a);
            a = fmaf(w.y, h[4 * c4 + 1], a);
            a = fmaf(w.z, h[4 * c4 + 2], a);
            a = fmaf(w.w, h[4 * c4 + 3], a);
        }
        dp[dch * 256] += a;
    }
}

// ---------------------------------------------------------------------------
// Kernel 7: recompose + output MLP (64 -> 128 gelu -> 1).
// ---------------------------------------------------------------------------
__global__ __launch_bounds__(256) void k_output(
    const float* __restrict__ W1, const float* __restrict__ b1,
    const float* __restrict__ W2, const float* __restrict__ b2,
    float* __restrict__ out)
{
    __shared__ float w1s[HID * E], b1s[HID], w2s[HID], b2s[1];
    int t = threadIdx.x;
    for (int i = t; i < HID * E; i += 256) w1s[i] = W1[i];
    if (t < HID) { b1s[t] = b1[t]; w2s[t] = W2[t]; }
    if (t == 0) b2s[0] = b2[0];
    __syncthreads();

    float u[E];
    const float* dp = &g_d[(size_t)blockIdx.x * TOKF + t];
#pragma unroll
    for (int c = 0; c < E; c++) u[c] = dp[c * 256];

    float acc = b2s[0];
    for (int hd = 0; hd < HID; hd++) {
        float a = b1s[hd];
        const float4* wr = (const float4*)&w1s[hd * 64];
#pragma unroll
        for (int c4 = 0; c4 < 16; c4++) {
            float4 w = wr[c4];
            a = fmaf(w.x, u[4 * c4 + 0], a);
            a = fmaf(w.y, u[4 * c4 + 1], a);
            a = fmaf(w.z, u[4 * c4 + 2], a);
            a = fmaf(w.w, u[4 * c4 + 3], a);
        }
        acc = fmaf(w2s[hd], gelu_exact(a), acc);
    }

    int bw = blockIdx.x >> 4, s = blockIdx.x & 15;
    int b = bw >> 4, wy = (bw >> 2) & 3, wx = bw & 3;
    int sy = s >> 2, sx = s & 3;
    int y = (wy * 4 + sy) * 16 + (t >> 4);
    int x = (wx * 4 + sx) * 16 + (t & 15);
    out[(size_t)b * 65536 + y * 256 + x] = acc;
}

// ---------------------------------------------------------------------------
extern "C" void kernel_launch(void* const* d_in, const int* in_sizes, int n_in,
                              void* d_out, int out_size)
{
    const float* v     = (const float*)d_in[0];
    const float* iW1   = (const float*)d_in[1];
    const float* ib1   = (const float*)d_in[2];
    const float* iW2   = (const float*)d_in[3];
    const float* ib2   = (const float*)d_in[4];
    const float* Wq    = (const float*)d_in[5];
    const float* bq    = (const float*)d_in[6];
    const float* Wk    = (const float*)d_in[7];
    const float* bk    = (const float*)d_in[8];
    const float* Wv    = (const float*)d_in[9];
    const float* bv    = (const float*)d_in[10];
    const float* Wo    = (const float*)d_in[11];
    const float* bo    = (const float*)d_in[12];
    const float* mW1   = (const float*)d_in[13];
    const float* mb1   = (const float*)d_in[14];
    const float* mW2   = (const float*)d_in[15];
    const float* mb2   = (const float*)d_in[16];
    const float* oW1   = (const float*)d_in[17];
    const float* ob1   = (const float*)d_in[18];
    const float* oW2   = (const float*)d_in[19];
    const float* ob2   = (const float*)d_in[20];
    float* out = (float*)d_out;

    const size_t sm_qkv = 13632 * sizeof(float);   // 54528 B
    const size_t sm_mlp = 24832 * sizeof(float);   // 99328 B
    cudaFuncSetAttribute(k_norm_qkv, cudaFuncAttributeMaxDynamicSharedMemorySize, (int)sm_qkv);
    cudaFuncSetAttribute(k_mlp,      cudaFuncAttributeMaxDynamicSharedMemorySize, (int)sm_mlp);

    k_input<<<NTOK, 256>>>(v, iW1, ib1, iW2, ib2);

    for (int l = 0; l < 4; l++) {
        int shift = (l & 1) ? 2 : 0;
        k_norm_qkv<<<NTOK, 256, sm_qkv>>>(Wq + l * 4096, bq + l * 64,
                                          Wk + l * 4096, bk + l * 64,
                                          Wv + l * 4096, bv + l * 64, shift);
        k_scores<<<dim3(4, NH, NWIN), 256>>>();
        k_attnA<<<NWIN, 512>>>();
        k_attnB<<<NTOK, 256>>>(Wo + l * 4096, bo + l * 64, shift);
        k_mlp<<<NTOK, 256, sm_mlp>>>(mW1 + l * 4096, mb1 + l * 64,
                                     mW2 + l * 4096, mb2 + l * 64);
    }

    k_output<<<NTOK, 256>>>(oW1, ob1, oW2, ob2, out);
}